// round 4
// baseline (speedup 1.0000x reference)
#include <cuda_runtime.h>
#include <cstdint>

// QuantumOperator closed form:
//   d_j = sigmoid(p_j) - p_j^2
//   out_real[j] = (sr.p + sum(si)) * p_j + d_j * sr[j] - si.p
//   out_imag[j] = (si.p - sum(sr)) * p_j + d_j * si[j] + sr.p
//
// R4: TMA bulk-load pipeline. 1 block/SM, 6-stage x 32KB SMEM ring filled by
// cp.async.bulk (16KB contiguous per array per stage). Each block owns a
// contiguous chunk span -> long same-page DRAM bursts + ~190KB reads in
// flight per SM. Compute from SMEM, streaming STG out.

#define DIM 128
#define ROWS_PER_CHUNK 32
#define STAGES 6
#define NWARPS 16
#define THREADS (NWARPS * 32)
#define CHUNK_FLOATS (ROWS_PER_CHUNK * DIM)          // 4096 floats = 16 KB
#define CHUNK_BYTES (CHUNK_FLOATS * 4)               // 16384
#define STAGE_FLOATS (CHUNK_FLOATS * 2)              // sr + si
#define SMEM_BYTES (STAGES * STAGE_FLOATS * 4)       // 196608 = 192 KB

__device__ __forceinline__ uint32_t s2u(const void* p) {
    return (uint32_t)__cvta_generic_to_shared(p);
}
__device__ __forceinline__ void mbar_init(uint32_t a, uint32_t cnt) {
    asm volatile("mbarrier.init.shared.b64 [%0], %1;" :: "r"(a), "r"(cnt) : "memory");
}
__device__ __forceinline__ void mbar_expect_tx(uint32_t a, uint32_t bytes) {
    asm volatile("mbarrier.arrive.expect_tx.shared.b64 _, [%0], %1;"
                 :: "r"(a), "r"(bytes) : "memory");
}
__device__ __forceinline__ void mbar_arrive(uint32_t a) {
    asm volatile("mbarrier.arrive.shared.b64 _, [%0];" :: "r"(a) : "memory");
}
__device__ __forceinline__ void mbar_wait(uint32_t a, uint32_t parity) {
    asm volatile(
        "{\n\t"
        ".reg .pred p%=;\n"
        "LW%=:\n\t"
        "mbarrier.try_wait.parity.acquire.cta.shared::cta.b64 p%=, [%0], %1, 0x989680;\n\t"
        "@p%= bra LD%=;\n\t"
        "bra LW%=;\n"
        "LD%=:\n\t"
        "}"
        :: "r"(a), "r"(parity) : "memory");
}
__device__ __forceinline__ void bulk_g2s(uint32_t dst, const void* src,
                                         uint32_t bytes, uint32_t mbar) {
    asm volatile(
        "cp.async.bulk.shared::cta.global.mbarrier::complete_tx::bytes [%0], [%1], %2, [%3];"
        :: "r"(dst), "l"(src), "r"(bytes), "r"(mbar) : "memory");
}

__device__ __forceinline__ float dot4(const float4 a, const float4 b) {
    return a.x * b.x + a.y * b.y + a.z * b.z + a.w * b.w;
}
__device__ __forceinline__ float hsum4(const float4 a) {
    return a.x + a.y + a.z + a.w;
}

__global__ void __launch_bounds__(THREADS, 1) quantum_tma_kernel(
    const float* __restrict__ gsr,
    const float* __restrict__ gsi,
    const float* __restrict__ p,
    float4* __restrict__ out_real,
    float4* __restrict__ out_imag,
    int nchunks_total, int chunks_per_block)
{
    extern __shared__ float smem[];
    __shared__ alignas(8) unsigned long long mbf[STAGES];
    __shared__ alignas(8) unsigned long long mbe[STAGES];

    const int tid = threadIdx.x;
    const int wid = tid >> 5;
    const int lane = tid & 31;

    if (tid == 0) {
        #pragma unroll
        for (int s = 0; s < STAGES; s++) {
            mbar_init(s2u(&mbf[s]), 1);
            mbar_init(s2u(&mbe[s]), NWARPS);
        }
        asm volatile("fence.proxy.async.shared::cta;" ::: "memory");
    }
    __syncthreads();

    const float4 p4 = reinterpret_cast<const float4*>(p)[lane];
    float4 d4;
    d4.x = 1.0f / (1.0f + __expf(-p4.x)) - p4.x * p4.x;
    d4.y = 1.0f / (1.0f + __expf(-p4.y)) - p4.y * p4.y;
    d4.z = 1.0f / (1.0f + __expf(-p4.z)) - p4.z * p4.z;
    d4.w = 1.0f / (1.0f + __expf(-p4.w)) - p4.w * p4.w;

    const int c0 = blockIdx.x * chunks_per_block;
    const int c1 = min(nchunks_total, c0 + chunks_per_block);
    const int nc = c1 - c0;
    if (nc <= 0) return;

    // Prologue: fill the ring
    if (tid == 0) {
        const int pre = nc < STAGES ? nc : STAGES;
        for (int k = 0; k < pre; k++) {
            const uint32_t mb = s2u(&mbf[k]);
            mbar_expect_tx(mb, 2 * CHUNK_BYTES);
            const uint32_t dsr = s2u(&smem[k * STAGE_FLOATS]);
            bulk_g2s(dsr, gsr + (size_t)(c0 + k) * CHUNK_FLOATS, CHUNK_BYTES, mb);
            bulk_g2s(dsr + CHUNK_BYTES, gsi + (size_t)(c0 + k) * CHUNK_FLOATS, CHUNK_BYTES, mb);
        }
    }

    const int r0 = 2 * wid;
    const int r1 = 2 * wid + 1;

    for (int k = 0; k < nc; k++) {
        const int s = k % STAGES;
        const int u = k / STAGES;
        mbar_wait(s2u(&mbf[s]), u & 1);

        const float4* bsr = reinterpret_cast<const float4*>(&smem[s * STAGE_FLOATS]);
        const float4* bsi = bsr + ROWS_PER_CHUNK * 32;

        const float4 a0 = bsr[r0 * 32 + lane];
        const float4 a1 = bsr[r1 * 32 + lane];
        const float4 b0 = bsi[r0 * 32 + lane];
        const float4 b1 = bsi[r1 * 32 + lane];

        float ar0 = dot4(a0, p4), ai0 = dot4(b0, p4);
        float sr0 = hsum4(a0),    si0 = hsum4(b0);
        float ar1 = dot4(a1, p4), ai1 = dot4(b1, p4);
        float sr1 = hsum4(a1),    si1 = hsum4(b1);

        #pragma unroll
        for (int off = 16; off > 0; off >>= 1) {
            ar0 += __shfl_xor_sync(0xFFFFFFFFu, ar0, off);
            ai0 += __shfl_xor_sync(0xFFFFFFFFu, ai0, off);
            sr0 += __shfl_xor_sync(0xFFFFFFFFu, sr0, off);
            si0 += __shfl_xor_sync(0xFFFFFFFFu, si0, off);
            ar1 += __shfl_xor_sync(0xFFFFFFFFu, ar1, off);
            ai1 += __shfl_xor_sync(0xFFFFFFFFu, ai1, off);
            sr1 += __shfl_xor_sync(0xFFFFFFFFu, sr1, off);
            si1 += __shfl_xor_sync(0xFFFFFFFFu, si1, off);
        }

        const size_t grow = (size_t)(c0 + k) * ROWS_PER_CHUNK;
        {
            const float cr = ar0 + si0, ci = ai0 - sr0;
            float4 orr, oii;
            orr.x = cr * p4.x + d4.x * a0.x - ai0;
            orr.y = cr * p4.y + d4.y * a0.y - ai0;
            orr.z = cr * p4.z + d4.z * a0.z - ai0;
            orr.w = cr * p4.w + d4.w * a0.w - ai0;
            oii.x = ci * p4.x + d4.x * b0.x + ar0;
            oii.y = ci * p4.y + d4.y * b0.y + ar0;
            oii.z = ci * p4.z + d4.z * b0.z + ar0;
            oii.w = ci * p4.w + d4.w * b0.w + ar0;
            __stcs(&out_real[(grow + r0) * 32 + lane], orr);
            __stcs(&out_imag[(grow + r0) * 32 + lane], oii);
        }
        {
            const float cr = ar1 + si1, ci = ai1 - sr1;
            float4 orr, oii;
            orr.x = cr * p4.x + d4.x * a1.x - ai1;
            orr.y = cr * p4.y + d4.y * a1.y - ai1;
            orr.z = cr * p4.z + d4.z * a1.z - ai1;
            orr.w = cr * p4.w + d4.w * a1.w - ai1;
            oii.x = ci * p4.x + d4.x * b1.x + ar1;
            oii.y = ci * p4.y + d4.y * b1.y + ar1;
            oii.z = ci * p4.z + d4.z * b1.z + ar1;
            oii.w = ci * p4.w + d4.w * b1.w + ar1;
            __stcs(&out_real[(grow + r1) * 32 + lane], orr);
            __stcs(&out_imag[(grow + r1) * 32 + lane], oii);
        }

        // Release the stage (one arrival per warp; count = NWARPS)
        if (lane == 0) mbar_arrive(s2u(&mbe[s]));

        // Producer: refill this stage for chunk k+STAGES once all warps released it
        if (tid == 0) {
            const int nk = k + STAGES;
            if (nk < nc) {
                mbar_wait(s2u(&mbe[s]), u & 1);
                const uint32_t mb = s2u(&mbf[s]);
                mbar_expect_tx(mb, 2 * CHUNK_BYTES);
                const uint32_t dsr = s2u(&smem[s * STAGE_FLOATS]);
                bulk_g2s(dsr, gsr + (size_t)(c0 + nk) * CHUNK_FLOATS, CHUNK_BYTES, mb);
                bulk_g2s(dsr + CHUNK_BYTES, gsi + (size_t)(c0 + nk) * CHUNK_FLOATS, CHUNK_BYTES, mb);
            }
        }
    }
}

extern "C" void kernel_launch(void* const* d_in, const int* in_sizes, int n_in,
                              void* d_out, int out_size) {
    const float* sr = (const float*)d_in[0];
    const float* si = (const float*)d_in[1];
    const float* p  = (const float*)d_in[2];
    float* out = (float*)d_out;

    const int M = in_sizes[0] / DIM;                 // 262144 rows
    float4* out_real = (float4*)out;
    float4* out_imag = (float4*)(out + (size_t)M * DIM);

    const int nchunks = M / ROWS_PER_CHUNK;          // 8192
    const int blocks = 152;                          // 1 block/SM on GB300
    const int cpb = (nchunks + blocks - 1) / blocks; // 54

    cudaFuncSetAttribute(quantum_tma_kernel,
                         cudaFuncAttributeMaxDynamicSharedMemorySize, SMEM_BYTES);
    quantum_tma_kernel<<<blocks, THREADS, SMEM_BYTES>>>(
        sr, si, p, out_real, out_imag, nchunks, cpb);
}

// round 5
// speedup vs baseline: 2.9137x; 2.9137x over previous
#include <cuda_runtime.h>

// QuantumOperator closed form:
//   d_j = sigmoid(p_j) - p_j^2
//   out_real[j] = (sr.p + sum(si)) * p_j + d_j * sr[j] - si.p
//   out_imag[j] = (si.p - sum(sr)) * p_j + d_j * si[j] + sr.p
//
// R5: persistent warps, contiguous per-warp row spans (sequential streaming
// per warp -> page/prefetch friendly DRAM request stream), 2 rows/iter,
// 4x LDG.128 back-to-back, __ldcg / __stcs. Grid = 5 blocks/SM exactly.

#define DIM 128

__device__ __forceinline__ float dot4(const float4 a, const float4 b) {
    return a.x * b.x + a.y * b.y + a.z * b.z + a.w * b.w;
}
__device__ __forceinline__ float hsum4(const float4 a) {
    return a.x + a.y + a.z + a.w;
}

__global__ void __launch_bounds__(256) quantum_op_kernel(
    const float4* __restrict__ srv,
    const float4* __restrict__ siv,
    const float* __restrict__ p,
    float4* __restrict__ out_real,
    float4* __restrict__ out_imag,
    int M, int rows_per_warp)
{
    const int lane = threadIdx.x & 31;
    const int warp = blockIdx.x * (blockDim.x >> 5) + (threadIdx.x >> 5);

    const float4 p4 = reinterpret_cast<const float4*>(p)[lane];
    float4 d4;
    d4.x = 1.0f / (1.0f + __expf(-p4.x)) - p4.x * p4.x;
    d4.y = 1.0f / (1.0f + __expf(-p4.y)) - p4.y * p4.y;
    d4.z = 1.0f / (1.0f + __expf(-p4.z)) - p4.z * p4.z;
    d4.w = 1.0f / (1.0f + __expf(-p4.w)) - p4.w * p4.w;

    // Contiguous row span for this warp
    int row = warp * rows_per_warp;
    int rend = row + rows_per_warp;
    if (rend > M) rend = M;

    for (; row + 1 < rend; row += 2) {
        // ---- 4x LDG.128 back-to-back (sequential addresses per warp) ----
        const float4 a0 = __ldcg(&srv[(size_t)row * 32 + lane]);
        const float4 a1 = __ldcg(&srv[(size_t)(row + 1) * 32 + lane]);
        const float4 b0 = __ldcg(&siv[(size_t)row * 32 + lane]);
        const float4 b1 = __ldcg(&siv[(size_t)(row + 1) * 32 + lane]);

        float ar0 = dot4(a0, p4), ai0 = dot4(b0, p4);
        float sr0 = hsum4(a0),    si0 = hsum4(b0);
        float ar1 = dot4(a1, p4), ai1 = dot4(b1, p4);
        float sr1 = hsum4(a1),    si1 = hsum4(b1);

        #pragma unroll
        for (int off = 16; off > 0; off >>= 1) {
            ar0 += __shfl_xor_sync(0xFFFFFFFFu, ar0, off);
            ai0 += __shfl_xor_sync(0xFFFFFFFFu, ai0, off);
            sr0 += __shfl_xor_sync(0xFFFFFFFFu, sr0, off);
            si0 += __shfl_xor_sync(0xFFFFFFFFu, si0, off);
            ar1 += __shfl_xor_sync(0xFFFFFFFFu, ar1, off);
            ai1 += __shfl_xor_sync(0xFFFFFFFFu, ai1, off);
            sr1 += __shfl_xor_sync(0xFFFFFFFFu, sr1, off);
            si1 += __shfl_xor_sync(0xFFFFFFFFu, si1, off);
        }

        {
            const float cr = ar0 + si0, ci = ai0 - sr0;
            float4 orr, oii;
            orr.x = cr * p4.x + d4.x * a0.x - ai0;
            orr.y = cr * p4.y + d4.y * a0.y - ai0;
            orr.z = cr * p4.z + d4.z * a0.z - ai0;
            orr.w = cr * p4.w + d4.w * a0.w - ai0;
            oii.x = ci * p4.x + d4.x * b0.x + ar0;
            oii.y = ci * p4.y + d4.y * b0.y + ar0;
            oii.z = ci * p4.z + d4.z * b0.z + ar0;
            oii.w = ci * p4.w + d4.w * b0.w + ar0;
            __stcs(&out_real[(size_t)row * 32 + lane], orr);
            __stcs(&out_imag[(size_t)row * 32 + lane], oii);
        }
        {
            const float cr = ar1 + si1, ci = ai1 - sr1;
            float4 orr, oii;
            orr.x = cr * p4.x + d4.x * a1.x - ai1;
            orr.y = cr * p4.y + d4.y * a1.y - ai1;
            orr.z = cr * p4.z + d4.z * a1.z - ai1;
            orr.w = cr * p4.w + d4.w * a1.w - ai1;
            oii.x = ci * p4.x + d4.x * b1.x + ar1;
            oii.y = ci * p4.y + d4.y * b1.y + ar1;
            oii.z = ci * p4.z + d4.z * b1.z + ar1;
            oii.w = ci * p4.w + d4.w * b1.w + ar1;
            __stcs(&out_real[(size_t)(row + 1) * 32 + lane], orr);
            __stcs(&out_imag[(size_t)(row + 1) * 32 + lane], oii);
        }
    }

    // Odd tail row (when rows_per_warp is odd or span clipped)
    if (row < rend) {
        const float4 a0 = __ldcg(&srv[(size_t)row * 32 + lane]);
        const float4 b0 = __ldcg(&siv[(size_t)row * 32 + lane]);
        float ar0 = dot4(a0, p4), ai0 = dot4(b0, p4);
        float sr0 = hsum4(a0),    si0 = hsum4(b0);
        #pragma unroll
        for (int off = 16; off > 0; off >>= 1) {
            ar0 += __shfl_xor_sync(0xFFFFFFFFu, ar0, off);
            ai0 += __shfl_xor_sync(0xFFFFFFFFu, ai0, off);
            sr0 += __shfl_xor_sync(0xFFFFFFFFu, sr0, off);
            si0 += __shfl_xor_sync(0xFFFFFFFFu, si0, off);
        }
        const float cr = ar0 + si0, ci = ai0 - sr0;
        float4 orr, oii;
        orr.x = cr * p4.x + d4.x * a0.x - ai0;
        orr.y = cr * p4.y + d4.y * a0.y - ai0;
        orr.z = cr * p4.z + d4.z * a0.z - ai0;
        orr.w = cr * p4.w + d4.w * a0.w - ai0;
        oii.x = ci * p4.x + d4.x * b0.x + ar0;
        oii.y = ci * p4.y + d4.y * b0.y + ar0;
        oii.z = ci * p4.z + d4.z * b0.z + ar0;
        oii.w = ci * p4.w + d4.w * b0.w + ar0;
        __stcs(&out_real[(size_t)row * 32 + lane], orr);
        __stcs(&out_imag[(size_t)row * 32 + lane], oii);
    }
}

extern "C" void kernel_launch(void* const* d_in, const int* in_sizes, int n_in,
                              void* d_out, int out_size) {
    const float* sr = (const float*)d_in[0];
    const float* si = (const float*)d_in[1];
    const float* p  = (const float*)d_in[2];
    float* out = (float*)d_out;

    const int M = in_sizes[0] / DIM;                 // 262144 rows
    float4* out_real = (float4*)out;
    float4* out_imag = (float4*)(out + (size_t)M * DIM);

    const int threads = 256;
    const int blocks = 760;                          // 5 blocks/SM x 152 SMs
    const int nwarps = blocks * (threads / 32);      // 6080
    const int rpw = (M + nwarps - 1) / nwarps;       // 44 contiguous rows/warp

    quantum_op_kernel<<<blocks, threads>>>(
        (const float4*)sr, (const float4*)si, p, out_real, out_imag, M, rpw);
}

// round 6
// speedup vs baseline: 3.3278x; 1.1421x over previous
#include <cuda_runtime.h>

// QuantumOperator closed form:
//   d_j = sigmoid(p_j) - p_j^2
//   out_real[j] = (sr.p + sum(si)) * p_j + d_j * sr[j] - si.p
//   out_imag[j] = (si.p - sum(sr)) * p_j + d_j * si[j] + sr.p
//
// R6: interleaved grid-stride (R3 layout, the proven best) with 4-row batch:
// 8x LDG.128 back-to-back (4KB same-direction read burst), 16 parallel
// butterfly chains, then 8x STG.128 back-to-back (4KB write burst).
// Goal: longer same-direction DRAM bursts -> fewer bus turnarounds.

#define DIM 128

__device__ __forceinline__ float dot4(const float4 a, const float4 b) {
    return a.x * b.x + a.y * b.y + a.z * b.z + a.w * b.w;
}
__device__ __forceinline__ float hsum4(const float4 a) {
    return a.x + a.y + a.z + a.w;
}

__global__ void __launch_bounds__(256) quantum_op_kernel(
    const float4* __restrict__ srv,
    const float4* __restrict__ siv,
    const float* __restrict__ p,
    float4* __restrict__ out_real,
    float4* __restrict__ out_imag,
    int M)
{
    const int lane = threadIdx.x & 31;
    const int warp = blockIdx.x * (blockDim.x >> 5) + (threadIdx.x >> 5);
    const int nwarps = gridDim.x * (blockDim.x >> 5);

    const float4 p4 = reinterpret_cast<const float4*>(p)[lane];
    float4 d4;
    d4.x = 1.0f / (1.0f + __expf(-p4.x)) - p4.x * p4.x;
    d4.y = 1.0f / (1.0f + __expf(-p4.y)) - p4.y * p4.y;
    d4.z = 1.0f / (1.0f + __expf(-p4.z)) - p4.z * p4.z;
    d4.w = 1.0f / (1.0f + __expf(-p4.w)) - p4.w * p4.w;

    const int stride = nwarps * 4;

    for (int row = warp * 4; row < M; row += stride) {
        const size_t base = (size_t)row * 32 + lane;

        // ---- 8x LDG.128 back-to-back: 4KB read burst per warp ----
        const float4 a0 = __ldcg(&srv[base]);
        const float4 a1 = __ldcg(&srv[base + 32]);
        const float4 a2 = __ldcg(&srv[base + 64]);
        const float4 a3 = __ldcg(&srv[base + 96]);
        const float4 b0 = __ldcg(&siv[base]);
        const float4 b1 = __ldcg(&siv[base + 32]);
        const float4 b2 = __ldcg(&siv[base + 64]);
        const float4 b3 = __ldcg(&siv[base + 96]);

        // ---- 16 independent butterfly chains ----
        float ar0 = dot4(a0, p4), ai0 = dot4(b0, p4), sr0 = hsum4(a0), si0 = hsum4(b0);
        float ar1 = dot4(a1, p4), ai1 = dot4(b1, p4), sr1 = hsum4(a1), si1 = hsum4(b1);
        float ar2 = dot4(a2, p4), ai2 = dot4(b2, p4), sr2 = hsum4(a2), si2 = hsum4(b2);
        float ar3 = dot4(a3, p4), ai3 = dot4(b3, p4), sr3 = hsum4(a3), si3 = hsum4(b3);

        #pragma unroll
        for (int off = 16; off > 0; off >>= 1) {
            ar0 += __shfl_xor_sync(0xFFFFFFFFu, ar0, off);
            ai0 += __shfl_xor_sync(0xFFFFFFFFu, ai0, off);
            sr0 += __shfl_xor_sync(0xFFFFFFFFu, sr0, off);
            si0 += __shfl_xor_sync(0xFFFFFFFFu, si0, off);
            ar1 += __shfl_xor_sync(0xFFFFFFFFu, ar1, off);
            ai1 += __shfl_xor_sync(0xFFFFFFFFu, ai1, off);
            sr1 += __shfl_xor_sync(0xFFFFFFFFu, sr1, off);
            si1 += __shfl_xor_sync(0xFFFFFFFFu, si1, off);
            ar2 += __shfl_xor_sync(0xFFFFFFFFu, ar2, off);
            ai2 += __shfl_xor_sync(0xFFFFFFFFu, ai2, off);
            sr2 += __shfl_xor_sync(0xFFFFFFFFu, sr2, off);
            si2 += __shfl_xor_sync(0xFFFFFFFFu, si2, off);
            ar3 += __shfl_xor_sync(0xFFFFFFFFu, ar3, off);
            ai3 += __shfl_xor_sync(0xFFFFFFFFu, ai3, off);
            sr3 += __shfl_xor_sync(0xFFFFFFFFu, sr3, off);
            si3 += __shfl_xor_sync(0xFFFFFFFFu, si3, off);
        }

        // ---- Compute all 8 output vectors, then store back-to-back ----
        float4 or0, or1, or2, or3, oi0, oi1, oi2, oi3;
        {
            const float cr = ar0 + si0, ci = ai0 - sr0;
            or0.x = cr * p4.x + d4.x * a0.x - ai0;
            or0.y = cr * p4.y + d4.y * a0.y - ai0;
            or0.z = cr * p4.z + d4.z * a0.z - ai0;
            or0.w = cr * p4.w + d4.w * a0.w - ai0;
            oi0.x = ci * p4.x + d4.x * b0.x + ar0;
            oi0.y = ci * p4.y + d4.y * b0.y + ar0;
            oi0.z = ci * p4.z + d4.z * b0.z + ar0;
            oi0.w = ci * p4.w + d4.w * b0.w + ar0;
        }
        {
            const float cr = ar1 + si1, ci = ai1 - sr1;
            or1.x = cr * p4.x + d4.x * a1.x - ai1;
            or1.y = cr * p4.y + d4.y * a1.y - ai1;
            or1.z = cr * p4.z + d4.z * a1.z - ai1;
            or1.w = cr * p4.w + d4.w * a1.w - ai1;
            oi1.x = ci * p4.x + d4.x * b1.x + ar1;
            oi1.y = ci * p4.y + d4.y * b1.y + ar1;
            oi1.z = ci * p4.z + d4.z * b1.z + ar1;
            oi1.w = ci * p4.w + d4.w * b1.w + ar1;
        }
        {
            const float cr = ar2 + si2, ci = ai2 - sr2;
            or2.x = cr * p4.x + d4.x * a2.x - ai2;
            or2.y = cr * p4.y + d4.y * a2.y - ai2;
            or2.z = cr * p4.z + d4.z * a2.z - ai2;
            or2.w = cr * p4.w + d4.w * a2.w - ai2;
            oi2.x = ci * p4.x + d4.x * b2.x + ar2;
            oi2.y = ci * p4.y + d4.y * b2.y + ar2;
            oi2.z = ci * p4.z + d4.z * b2.z + ar2;
            oi2.w = ci * p4.w + d4.w * b2.w + ar2;
        }
        {
            const float cr = ar3 + si3, ci = ai3 - sr3;
            or3.x = cr * p4.x + d4.x * a3.x - ai3;
            or3.y = cr * p4.y + d4.y * a3.y - ai3;
            or3.z = cr * p4.z + d4.z * a3.z - ai3;
            or3.w = cr * p4.w + d4.w * a3.w - ai3;
            oi3.x = ci * p4.x + d4.x * b3.x + ar3;
            oi3.y = ci * p4.y + d4.y * b3.y + ar3;
            oi3.z = ci * p4.z + d4.z * b3.z + ar3;
            oi3.w = ci * p4.w + d4.w * b3.w + ar3;
        }

        __stcs(&out_real[base],      or0);
        __stcs(&out_real[base + 32], or1);
        __stcs(&out_real[base + 64], or2);
        __stcs(&out_real[base + 96], or3);
        __stcs(&out_imag[base],      oi0);
        __stcs(&out_imag[base + 32], oi1);
        __stcs(&out_imag[base + 64], oi2);
        __stcs(&out_imag[base + 96], oi3);
    }
}

extern "C" void kernel_launch(void* const* d_in, const int* in_sizes, int n_in,
                              void* d_out, int out_size) {
    const float* sr = (const float*)d_in[0];
    const float* si = (const float*)d_in[1];
    const float* p  = (const float*)d_in[2];
    float* out = (float*)d_out;

    const int M = in_sizes[0] / DIM;                 // 262144 rows
    float4* out_real = (float4*)out;
    float4* out_imag = (float4*)(out + (size_t)M * DIM);

    const int threads = 256;
    const int blocks = 2048;      // 16384 warps x 4 rows = 65536 rows/sweep, 4 sweeps
    quantum_op_kernel<<<blocks, threads>>>(
        (const float4*)sr, (const float4*)si, p, out_real, out_imag, M);
}